// round 8
// baseline (speedup 1.0000x reference)
#include <cuda_runtime.h>

typedef unsigned long long u64;

// ---------- packed f32x2 helpers (sm_103a FFMA2 only via PTX) ----------
__device__ __forceinline__ u64 pack2(float lo, float hi){
    u64 r; asm("mov.b64 %0, {%1,%2};" : "=l"(r) : "f"(lo), "f"(hi)); return r;
}
__device__ __forceinline__ void unpack2(u64 v, float &lo, float &hi){
    asm("mov.b64 {%0,%1}, %2;" : "=f"(lo), "=f"(hi) : "l"(v));
}
__device__ __forceinline__ u64 mul2(u64 a, u64 b){
    u64 r; asm("mul.rn.f32x2 %0, %1, %2;" : "=l"(r) : "l"(a), "l"(b)); return r;
}
__device__ __forceinline__ void fma2(u64 &d, u64 a, u64 b){
    asm("fma.rn.f32x2 %0, %1, %2, %0;" : "+l"(d) : "l"(a), "l"(b));
}

// ---------- symmetrized coefficient tables (written by prep each launch) ----
__device__ __align__(16) u64 g_C1[9 * 4];      // deg-1: 9 monos x 4 cols
__device__ __align__(16) u64 g_C2[45 * 8];     // deg-2: 45 monos x 8 cols
__device__ __align__(16) u64 g_C3[165 * 16];   // deg-3: 165 monos x 12 cols,
                                               // padded: col c at (c/3)*4 + c%3

__device__ __forceinline__ float fetch3(const float* __restrict__ b30,
                                        const float* __restrict__ b31,
                                        int i, int j, int k, int c){
    int base = ((i * 9 + j) * 9 + k) * 3;         // b30: (9,9,9,3,1); b31: (9,9,9,3,3)
    if (c < 3) return b30[base + c];
    return b31[base * 3 + (c - 3)];
}

__global__ void prep_kernel(const float* __restrict__ b10, const float* __restrict__ b11,
                            const float* __restrict__ b20, const float* __restrict__ b21,
                            const float* __restrict__ b30, const float* __restrict__ b31){
    int tid = blockIdx.x * blockDim.x + threadIdx.x;

    if (tid < 36){
        int a = tid >> 2, c = tid & 3;
        float v = (c == 0) ? b10[a] : b11[a * 3 + c - 1];
        g_C1[tid] = pack2(v, v);
    }

    int t2 = tid - 64;
    if (t2 >= 0 && t2 < 45 * 8){
        int mono = t2 >> 3, c = t2 & 7;
        int a = 0, rem = mono;
        while (rem >= 9 - a){ rem -= 9 - a; a++; }
        int b = a + rem;                            // a <= b
        float v;
        if (c < 2){                                 // b20: (9,9,2,1)
            v = b20[(a * 9 + b) * 2 + c];
            if (a != b) v += b20[(b * 9 + a) * 2 + c];
        } else {                                    // b21: (9,9,2,3); c-2 = s*3+p
            int sp = c - 2;
            v = b21[(a * 9 + b) * 6 + sp];
            if (a != b) v += b21[(b * 9 + a) * 6 + sp];
        }
        g_C2[t2] = pack2(v, v);
    }

    int t3 = tid - 448;
    if (t3 >= 0 && t3 < 165 * 12){
        int mono = t3 / 12, c = t3 % 12;
        int a = 0, rem = mono;
        while (true){ int cnt = (9 - a) * (10 - a) / 2; if (rem < cnt) break; rem -= cnt; a++; }
        int b = a;
        while (rem >= 9 - b){ rem -= 9 - b; b++; }
        int k = b + rem;                            // a <= b <= k
        float v = fetch3(b30, b31, a, b, k, c);
        if (a == b && b == k){
        } else if (a == b){
            v += fetch3(b30, b31, a, k, b, c) + fetch3(b30, b31, k, a, b, c);
        } else if (b == k){
            v += fetch3(b30, b31, b, a, k, c) + fetch3(b30, b31, b, k, a, c);
        } else {
            v += fetch3(b30, b31, a, k, b, c) + fetch3(b30, b31, b, a, k, c)
               + fetch3(b30, b31, b, k, a, c) + fetch3(b30, b31, k, a, b, c)
               + fetch3(b30, b31, k, b, a, c);
        }
        // padded layout: group of 3 cols per colQ lives at colQ*4 + {0,1,2}
        g_C3[mono * 16 + (c / 3) * 4 + (c % 3)] = pack2(v, v);
    }
}

// ---------- main kernel ------------------------------------------------------
// 1 block = 1 node, 128 threads. Lane quad (4q..4q+3) covers channel quad
// m0 = 4q; colQ = tl&3 selects a quarter of the output columns:
//   C1: col colQ | C2: cols 2colQ..2colQ+1 | C3: cols 3colQ..3colQ+2
// Per-thread accumulators: (1+2+3) cols x 2 ch-pairs = 12 u64 (24 regs).
// 4-lane shuffle reduction at the end.
__global__ void __launch_bounds__(128) mace_kernel(
    const float* __restrict__ nf, const int* __restrict__ species,
    const float* __restrict__ w10, const float* __restrict__ w11,
    const float* __restrict__ w20, const float* __restrict__ w21,
    const float* __restrict__ w30, const float* __restrict__ w31,
    float* __restrict__ out)
{
    __shared__ __align__(16) u64 sC1[9 * 4];
    __shared__ __align__(16) u64 sC2[45 * 8];
    __shared__ __align__(16) u64 sC3[165 * 16];

    const int t = threadIdx.x;
    for (int i = t; i < 36;   i += 128) sC1[i] = g_C1[i];
    for (int i = t; i < 360;  i += 128) sC2[i] = g_C2[i];
    for (int i = t; i < 2640; i += 128) sC3[i] = g_C3[i];
    __syncthreads();

    const int node = blockIdx.x;
    const int q    = t >> 2;              // channel quad [0,32)
    const int colQ = t & 3;               // column quarter
    const int m0   = q * 4;               // channels m0..m0+3 (pair A, pair B)
    const float* nfp = nf + (size_t)node * 1152;

    // x components fully in registers.
    u64 xA[9], xB[9];
    {
        float4 v = *(const float4*)(nfp + m0);
        xA[0] = pack2(v.x, v.y);
        xB[0] = pack2(v.z, v.w);
    }
    #pragma unroll
    for (int j = 0; j < 3; j++){
        xA[1 + j] = pack2(nfp[128 + m0 * 3 + j],      nfp[128 + m0 * 3 + 3 + j]);
        xB[1 + j] = pack2(nfp[128 + m0 * 3 + 6 + j],  nfp[128 + m0 * 3 + 9 + j]);
    }
    #pragma unroll
    for (int j = 0; j < 5; j++){
        xA[4 + j] = pack2(nfp[512 + m0 * 5 + j],      nfp[512 + m0 * 5 + 5 + j]);
        xB[4 + j] = pack2(nfp[512 + m0 * 5 + 10 + j], nfp[512 + m0 * 5 + 15 + j]);
    }

    // Per-thread accumulators: P1 (C1 col), P2[2] (C2 cols), P3[3] (C3 cols)
    u64 P1A = 0ull, P1B = 0ull;
    u64 P2A[2] = {0ull, 0ull}, P2B[2] = {0ull, 0ull};
    u64 P3A[3] = {0ull, 0ull, 0ull}, P3B[3] = {0ull, 0ull, 0ull};

    const int o2 = colQ * 2;
    const int o3 = colQ * 4;

    int i2 = 0, i3 = 0;                       // constant-folded by full unroll
    #pragma unroll
    for (int a = 0; a < 9; a++){
        {
            u64 c = sC1[a * 4 + colQ];
            fma2(P1A, c, xA[a]);  fma2(P1B, c, xB[a]);
        }
        #pragma unroll
        for (int b = a; b < 9; b++){
            u64 pabA = mul2(xA[a], xA[b]);
            u64 pabB = mul2(xB[a], xB[b]);
            {
                ulonglong2 c = *(const ulonglong2*)(sC2 + i2 * 8 + o2);
                fma2(P2A[0], c.x, pabA);  fma2(P2B[0], c.x, pabB);
                fma2(P2A[1], c.y, pabA);  fma2(P2B[1], c.y, pabB);
            }
            i2++;
            #pragma unroll
            for (int k = b; k < 9; k++){
                u64 p3A = mul2(pabA, xA[k]);
                u64 p3B = mul2(pabB, xB[k]);
                const u64* row = sC3 + i3 * 16 + o3;
                ulonglong2 c01 = *(const ulonglong2*)(row);
                u64 c2v = row[2];
                fma2(P3A[0], c01.x, p3A);  fma2(P3B[0], c01.x, p3B);
                fma2(P3A[1], c01.y, p3A);  fma2(P3B[1], c01.y, p3B);
                fma2(P3A[2], c2v,  p3A);   fma2(P3B[2], c2v,  p3B);
                i3++;
            }
        }
    }

    // ---- fold with per-(species, channel) weights --------------------------
    const int sp = species[node];
    const float* W10 = w10 + sp * 128;
    const float* W11 = w11 + sp * 128;
    const float* W20 = w20 + sp * 256;
    const float* W21 = w21 + sp * 256;
    const float* W30 = w30 + sp * 384;
    const float* W31 = w31 + sp * 384;

    u64 O0[2]  = {0ull, 0ull};
    u64 OP0[2] = {0ull, 0ull}, OP1[2] = {0ull, 0ull}, OP2[2] = {0ull, 0ull};

    #pragma unroll
    for (int h = 0; h < 2; h++){
        const int mc = m0 + 2 * h;
        u64 p1 = h ? P1B : P1A;
        u64* p2 = h ? P2B : P2A;
        u64* p3 = h ? P3B : P3A;
        if (colQ == 0){
            // C1 c0 -> O0 (w10); C2 c0,c1 -> O0 (w20 s0,s1); C3 c0..2 -> O0 (w30)
            fma2(O0[h], *(const u64*)(W10 + mc),       p1);
            fma2(O0[h], *(const u64*)(W20 + mc),       p2[0]);
            fma2(O0[h], *(const u64*)(W20 + 128 + mc), p2[1]);
            fma2(O0[h], *(const u64*)(W30 + mc),       p3[0]);
            fma2(O0[h], *(const u64*)(W30 + 128 + mc), p3[1]);
            fma2(O0[h], *(const u64*)(W30 + 256 + mc), p3[2]);
        } else if (colQ == 1){
            // C1 c1 = b11 p0 -> OP0 (w11); C2 c2,c3 = s0p0,s0p1 -> OP0,OP1 (w21 s0)
            // C3 c3..5 = s0 p0..2 -> OP0..2 (w31 s0)
            fma2(OP0[h], *(const u64*)(W11 + mc),       p1);
            fma2(OP0[h], *(const u64*)(W21 + mc),       p2[0]);
            fma2(OP1[h], *(const u64*)(W21 + mc),       p2[1]);
            fma2(OP0[h], *(const u64*)(W31 + mc),       p3[0]);
            fma2(OP1[h], *(const u64*)(W31 + mc),       p3[1]);
            fma2(OP2[h], *(const u64*)(W31 + mc),       p3[2]);
        } else if (colQ == 2){
            // C1 c2 = b11 p1 -> OP1 (w11); C2 c4 = s0p2 -> OP2 (w21 s0),
            // c5 = s1p0 -> OP0 (w21 s1); C3 c6..8 = s1 p0..2 -> OP0..2 (w31 s1)
            fma2(OP1[h], *(const u64*)(W11 + mc),       p1);
            fma2(OP2[h], *(const u64*)(W21 + mc),       p2[0]);
            fma2(OP0[h], *(const u64*)(W21 + 128 + mc), p2[1]);
            fma2(OP0[h], *(const u64*)(W31 + 128 + mc), p3[0]);
            fma2(OP1[h], *(const u64*)(W31 + 128 + mc), p3[1]);
            fma2(OP2[h], *(const u64*)(W31 + 128 + mc), p3[2]);
        } else {
            // C1 c3 = b11 p2 -> OP2 (w11); C2 c6,c7 = s1p1,s1p2 -> OP1,OP2 (w21 s1)
            // C3 c9..11 = s2 p0..2 -> OP0..2 (w31 s2)
            fma2(OP2[h], *(const u64*)(W11 + mc),       p1);
            fma2(OP1[h], *(const u64*)(W21 + 128 + mc), p2[0]);
            fma2(OP2[h], *(const u64*)(W21 + 128 + mc), p2[1]);
            fma2(OP0[h], *(const u64*)(W31 + 256 + mc), p3[0]);
            fma2(OP1[h], *(const u64*)(W31 + 256 + mc), p3[1]);
            fma2(OP2[h], *(const u64*)(W31 + 256 + mc), p3[2]);
        }
    }

    // ---- 4-lane reduction within the quad, lane colQ==0 stores --------------
    float r[16];
    #pragma unroll
    for (int h = 0; h < 2; h++){
        unpack2(O0[h],  r[h*8+0], r[h*8+1]);
        unpack2(OP0[h], r[h*8+2], r[h*8+3]);
        unpack2(OP1[h], r[h*8+4], r[h*8+5]);
        unpack2(OP2[h], r[h*8+6], r[h*8+7]);
    }
    #pragma unroll
    for (int i = 0; i < 16; i++){
        r[i] += __shfl_down_sync(0xFFFFFFFFu, r[i], 2);
        r[i] += __shfl_down_sync(0xFFFFFFFFu, r[i], 1);
    }

    if (colQ == 0){
        float* outp = out + (size_t)node * 512;
        *(float4*)(outp + m0) = make_float4(r[0], r[1], r[8], r[9]);
        #pragma unroll
        for (int h = 0; h < 2; h++){
            const int mc = m0 + 2 * h;
            outp[128 + mc * 3 + 0] = r[h*8+2];  outp[128 + mc * 3 + 3] = r[h*8+3];
            outp[128 + mc * 3 + 1] = r[h*8+4];  outp[128 + mc * 3 + 4] = r[h*8+5];
            outp[128 + mc * 3 + 2] = r[h*8+6];  outp[128 + mc * 3 + 5] = r[h*8+7];
        }
    }
}

extern "C" void kernel_launch(void* const* d_in, const int* in_sizes, int n_in,
                              void* d_out, int out_size){
    // metadata order is INTERLEAVED (b_i, w_i) pairs.
    const float* nf      = (const float*)d_in[0];
    const int*   species = (const int*)  d_in[1];
    const float* b10 = (const float*)d_in[2];
    const float* w10 = (const float*)d_in[3];
    const float* b11 = (const float*)d_in[4];
    const float* w11 = (const float*)d_in[5];
    const float* b20 = (const float*)d_in[6];
    const float* w20 = (const float*)d_in[7];
    const float* b21 = (const float*)d_in[8];
    const float* w21 = (const float*)d_in[9];
    const float* b30 = (const float*)d_in[10];
    const float* w30 = (const float*)d_in[11];
    const float* b31 = (const float*)d_in[12];
    const float* w31 = (const float*)d_in[13];

    const int n_nodes = in_sizes[1];   // species element count (2048)

    prep_kernel<<<19, 128>>>(b10, b11, b20, b21, b30, b31);
    // 1 block = 1 node, 128 threads (lane quads split output columns 4-way)
    mace_kernel<<<n_nodes, 128>>>(nf, species, w10, w11, w20, w21, w30, w31,
                                  (float*)d_out);
}

// round 9
// speedup vs baseline: 1.1699x; 1.1699x over previous
#include <cuda_runtime.h>

typedef unsigned long long u64;

// ---------- packed f32x2 helpers (sm_103a FFMA2 only via PTX) ----------
__device__ __forceinline__ u64 pack2(float lo, float hi){
    u64 r; asm("mov.b64 %0, {%1,%2};" : "=l"(r) : "f"(lo), "f"(hi)); return r;
}
__device__ __forceinline__ void unpack2(u64 v, float &lo, float &hi){
    asm("mov.b64 {%0,%1}, %2;" : "=f"(lo), "=f"(hi) : "l"(v));
}
__device__ __forceinline__ u64 mul2(u64 a, u64 b){
    u64 r; asm("mul.rn.f32x2 %0, %1, %2;" : "=l"(r) : "l"(a), "l"(b)); return r;
}
__device__ __forceinline__ void fma2(u64 &d, u64 a, u64 b){
    asm("fma.rn.f32x2 %0, %1, %2, %0;" : "+l"(d) : "l"(a), "l"(b));
}

// ---------- symmetrized coefficient tables (written by prep each launch) ----
__device__ __align__(16) u64 g_C1[9 * 4];      // deg-1: 9 monos x 4 cols
__device__ __align__(16) u64 g_C2[45 * 8];     // deg-2: 45 monos x 8 cols
__device__ __align__(16) u64 g_C3[165 * 12];   // deg-3: 165 monos x 12 cols

__device__ __forceinline__ float fetch3(const float* __restrict__ b30,
                                        const float* __restrict__ b31,
                                        int i, int j, int k, int c){
    int base = ((i * 9 + j) * 9 + k) * 3;         // b30: (9,9,9,3,1); b31: (9,9,9,3,3)
    if (c < 3) return b30[base + c];
    return b31[base * 3 + (c - 3)];
}

__global__ void prep_kernel(const float* __restrict__ b10, const float* __restrict__ b11,
                            const float* __restrict__ b20, const float* __restrict__ b21,
                            const float* __restrict__ b30, const float* __restrict__ b31){
    int tid = blockIdx.x * blockDim.x + threadIdx.x;

    if (tid < 36){
        int a = tid >> 2, c = tid & 3;
        float v = (c == 0) ? b10[a] : b11[a * 3 + c - 1];
        g_C1[tid] = pack2(v, v);
    }

    int t2 = tid - 64;
    if (t2 >= 0 && t2 < 45 * 8){
        int mono = t2 >> 3, c = t2 & 7;
        int a = 0, rem = mono;
        while (rem >= 9 - a){ rem -= 9 - a; a++; }
        int b = a + rem;                            // a <= b
        float v;
        if (c < 2){                                 // b20: (9,9,2,1)
            v = b20[(a * 9 + b) * 2 + c];
            if (a != b) v += b20[(b * 9 + a) * 2 + c];
        } else {                                    // b21: (9,9,2,3); c-2 = s*3+p
            int sp = c - 2;
            v = b21[(a * 9 + b) * 6 + sp];
            if (a != b) v += b21[(b * 9 + a) * 6 + sp];
        }
        g_C2[t2] = pack2(v, v);
    }

    int t3 = tid - 448;
    if (t3 >= 0 && t3 < 165 * 12){
        int mono = t3 / 12, c = t3 % 12;
        int a = 0, rem = mono;
        while (true){ int cnt = (9 - a) * (10 - a) / 2; if (rem < cnt) break; rem -= cnt; a++; }
        int b = a;
        while (rem >= 9 - b){ rem -= 9 - b; b++; }
        int k = b + rem;                            // a <= b <= k
        float v = fetch3(b30, b31, a, b, k, c);
        if (a == b && b == k){
        } else if (a == b){
            v += fetch3(b30, b31, a, k, b, c) + fetch3(b30, b31, k, a, b, c);
        } else if (b == k){
            v += fetch3(b30, b31, b, a, k, c) + fetch3(b30, b31, b, k, a, c);
        } else {
            v += fetch3(b30, b31, a, k, b, c) + fetch3(b30, b31, b, a, k, c)
               + fetch3(b30, b31, b, k, a, c) + fetch3(b30, b31, k, a, b, c)
               + fetch3(b30, b31, k, b, a, c);
        }
        g_C3[t3] = pack2(v, v);
    }
}

// ---------- main kernel ------------------------------------------------------
// 1 block = 4 nodes, 256 threads = 8 warps. Warp w covers (node_sub = w>>1,
// colHalf = w&1); its 32 lanes cover the node's 32 channel quads (4 ch/thread).
// colHalf is WARP-UNIFORM -> all coefficient LDS are true broadcasts.
//   colHalf 0 -> C1 cols 0,1 | C2 cols 0..3 | C3 cols 0..5
//   colHalf 1 -> C1 cols 2,3 | C2 cols 4..7 | C3 cols 6..11
// Halves combined through a smem partial buffer.
__global__ void __launch_bounds__(256) mace_kernel(
    const float* __restrict__ nf, const int* __restrict__ species,
    const float* __restrict__ w10, const float* __restrict__ w11,
    const float* __restrict__ w20, const float* __restrict__ w21,
    const float* __restrict__ w30, const float* __restrict__ w31,
    float* __restrict__ out)
{
    __shared__ __align__(16) u64 sC1[9 * 4];
    __shared__ __align__(16) u64 sC2[45 * 8];
    __shared__ __align__(16) u64 sC3[165 * 12];
    __shared__ float part[4][512];         // colHalf-1 partials per node

    const int t = threadIdx.x;
    for (int i = t; i < 36;   i += 256) sC1[i] = g_C1[i];
    for (int i = t; i < 360;  i += 256) sC2[i] = g_C2[i];
    for (int i = t; i < 1980; i += 256) sC3[i] = g_C3[i];
    __syncthreads();

    const int w        = t >> 5;          // warp id [0,8)
    const int lane     = t & 31;
    const int node_sub = w >> 1;          // [0,4)
    const int colHalf  = w & 1;           // warp-uniform column half
    const int node     = blockIdx.x * 4 + node_sub;
    const int m0       = lane * 4;        // channels m0..m0+3 (pair A, pair B)
    const float* nfp   = nf + (size_t)node * 1152;

    // x components fully in registers.
    u64 xA[9], xB[9];
    {
        float4 v = *(const float4*)(nfp + m0);
        xA[0] = pack2(v.x, v.y);
        xB[0] = pack2(v.z, v.w);
    }
    #pragma unroll
    for (int j = 0; j < 3; j++){
        xA[1 + j] = pack2(nfp[128 + m0 * 3 + j],      nfp[128 + m0 * 3 + 3 + j]);
        xB[1 + j] = pack2(nfp[128 + m0 * 3 + 6 + j],  nfp[128 + m0 * 3 + 9 + j]);
    }
    #pragma unroll
    for (int j = 0; j < 5; j++){
        xA[4 + j] = pack2(nfp[512 + m0 * 5 + j],      nfp[512 + m0 * 5 + 5 + j]);
        xB[4 + j] = pack2(nfp[512 + m0 * 5 + 10 + j], nfp[512 + m0 * 5 + 15 + j]);
    }

    // Per-thread moment accumulators for this column half:
    //  P*[0..1]  = C1 cols (colHalf*2 +0..1)
    //  P*[2..5]  = C2 cols (colHalf*4 +0..3)
    //  P*[6..11] = C3 cols (colHalf*6 +0..5)
    u64 PA[12], PB[12];
    #pragma unroll
    for (int i = 0; i < 12; i++){ PA[i] = 0ull; PB[i] = 0ull; }

    const int o1 = colHalf * 2;   // warp-uniform offsets
    const int o2 = colHalf * 4;
    const int o3 = colHalf * 6;

    int i2 = 0, i3 = 0;                       // constant-folded by full unroll
    #pragma unroll
    for (int a = 0; a < 9; a++){
        {
            ulonglong2 c0 = *(const ulonglong2*)(sC1 + a * 4 + o1);
            fma2(PA[0], c0.x, xA[a]);  fma2(PB[0], c0.x, xB[a]);
            fma2(PA[1], c0.y, xA[a]);  fma2(PB[1], c0.y, xB[a]);
        }
        #pragma unroll
        for (int b = a; b < 9; b++){
            u64 pabA = mul2(xA[a], xA[b]);
            u64 pabB = mul2(xB[a], xB[b]);
            {
                ulonglong2 c0 = *(const ulonglong2*)(sC2 + i2 * 8 + o2);
                ulonglong2 c1 = *(const ulonglong2*)(sC2 + i2 * 8 + o2 + 2);
                fma2(PA[2], c0.x, pabA);  fma2(PB[2], c0.x, pabB);
                fma2(PA[3], c0.y, pabA);  fma2(PB[3], c0.y, pabB);
                fma2(PA[4], c1.x, pabA);  fma2(PB[4], c1.x, pabB);
                fma2(PA[5], c1.y, pabA);  fma2(PB[5], c1.y, pabB);
            }
            i2++;
            #pragma unroll
            for (int k = b; k < 9; k++){
                u64 p3A = mul2(pabA, xA[k]);
                u64 p3B = mul2(pabB, xB[k]);
                ulonglong2 c0 = *(const ulonglong2*)(sC3 + i3 * 12 + o3);
                ulonglong2 c1 = *(const ulonglong2*)(sC3 + i3 * 12 + o3 + 2);
                ulonglong2 c2 = *(const ulonglong2*)(sC3 + i3 * 12 + o3 + 4);
                fma2(PA[6],  c0.x, p3A);  fma2(PB[6],  c0.x, p3B);
                fma2(PA[7],  c0.y, p3A);  fma2(PB[7],  c0.y, p3B);
                fma2(PA[8],  c1.x, p3A);  fma2(PB[8],  c1.x, p3B);
                fma2(PA[9],  c1.y, p3A);  fma2(PB[9],  c1.y, p3B);
                fma2(PA[10], c2.x, p3A);  fma2(PB[10], c2.x, p3B);
                fma2(PA[11], c2.y, p3A);  fma2(PB[11], c2.y, p3B);
                i3++;
            }
        }
    }

    // ---- fold with per-(species, channel) weights into output accumulators --
    const int sp = species[node];
    const float* W10 = w10 + sp * 128;
    const float* W11 = w11 + sp * 128;
    const float* W20 = w20 + sp * 256;
    const float* W21 = w21 + sp * 256;
    const float* W30 = w30 + sp * 384;
    const float* W31 = w31 + sp * 384;

    u64 O0[2]  = {0ull, 0ull};
    u64 OP0[2] = {0ull, 0ull}, OP1[2] = {0ull, 0ull}, OP2[2] = {0ull, 0ull};

    #pragma unroll
    for (int h = 0; h < 2; h++){
        const int mc = m0 + 2 * h;
        u64* P = h ? PB : PA;
        if (colHalf == 0){
            fma2(O0[h],  *(const u64*)(W10 + mc),       P[0]);
            fma2(OP0[h], *(const u64*)(W11 + mc),       P[1]);
            fma2(O0[h],  *(const u64*)(W20 + mc),       P[2]);
            fma2(O0[h],  *(const u64*)(W20 + 128 + mc), P[3]);
            fma2(OP0[h], *(const u64*)(W21 + mc),       P[4]);
            fma2(OP1[h], *(const u64*)(W21 + mc),       P[5]);
            fma2(O0[h],  *(const u64*)(W30 + mc),       P[6]);
            fma2(O0[h],  *(const u64*)(W30 + 128 + mc), P[7]);
            fma2(O0[h],  *(const u64*)(W30 + 256 + mc), P[8]);
            fma2(OP0[h], *(const u64*)(W31 + mc),       P[9]);
            fma2(OP1[h], *(const u64*)(W31 + mc),       P[10]);
            fma2(OP2[h], *(const u64*)(W31 + mc),       P[11]);
        } else {
            fma2(OP1[h], *(const u64*)(W11 + mc),       P[0]);
            fma2(OP2[h], *(const u64*)(W11 + mc),       P[1]);
            fma2(OP2[h], *(const u64*)(W21 + mc),       P[2]);
            fma2(OP0[h], *(const u64*)(W21 + 128 + mc), P[3]);
            fma2(OP1[h], *(const u64*)(W21 + 128 + mc), P[4]);
            fma2(OP2[h], *(const u64*)(W21 + 128 + mc), P[5]);
            fma2(OP0[h], *(const u64*)(W31 + 128 + mc), P[6]);
            fma2(OP1[h], *(const u64*)(W31 + 128 + mc), P[7]);
            fma2(OP2[h], *(const u64*)(W31 + 128 + mc), P[8]);
            fma2(OP0[h], *(const u64*)(W31 + 256 + mc), P[9]);
            fma2(OP1[h], *(const u64*)(W31 + 256 + mc), P[10]);
            fma2(OP2[h], *(const u64*)(W31 + 256 + mc), P[11]);
        }
    }

    // ---- combine halves through smem, colHalf-0 warp stores ------------------
    float r[16];  // [h][acc: O0,OP0,OP1,OP2][lo/hi]
    #pragma unroll
    for (int h = 0; h < 2; h++){
        unpack2(O0[h],  r[h*8+0], r[h*8+1]);
        unpack2(OP0[h], r[h*8+2], r[h*8+3]);
        unpack2(OP1[h], r[h*8+4], r[h*8+5]);
        unpack2(OP2[h], r[h*8+6], r[h*8+7]);
    }

    if (colHalf == 1){
        float* p = part[node_sub];
        p[m0 + 0] = r[0];  p[m0 + 1] = r[1];
        p[m0 + 2] = r[8];  p[m0 + 3] = r[9];
        #pragma unroll
        for (int h = 0; h < 2; h++){
            const int mc = m0 + 2 * h;
            p[128 + mc * 3 + 0] = r[h*8+2];  p[128 + mc * 3 + 3] = r[h*8+3];
            p[128 + mc * 3 + 1] = r[h*8+4];  p[128 + mc * 3 + 4] = r[h*8+5];
            p[128 + mc * 3 + 2] = r[h*8+6];  p[128 + mc * 3 + 5] = r[h*8+7];
        }
    }
    __syncthreads();
    if (colHalf == 0){
        const float* p = part[node_sub];
        float* outp = out + (size_t)node * 512;
        *(float4*)(outp + m0) = make_float4(
            r[0] + p[m0 + 0], r[1] + p[m0 + 1],
            r[8] + p[m0 + 2], r[9] + p[m0 + 3]);
        #pragma unroll
        for (int h = 0; h < 2; h++){
            const int mc = m0 + 2 * h;
            outp[128 + mc * 3 + 0] = r[h*8+2] + p[128 + mc * 3 + 0];
            outp[128 + mc * 3 + 3] = r[h*8+3] + p[128 + mc * 3 + 3];
            outp[128 + mc * 3 + 1] = r[h*8+4] + p[128 + mc * 3 + 1];
            outp[128 + mc * 3 + 4] = r[h*8+5] + p[128 + mc * 3 + 4];
            outp[128 + mc * 3 + 2] = r[h*8+6] + p[128 + mc * 3 + 2];
            outp[128 + mc * 3 + 5] = r[h*8+7] + p[128 + mc * 3 + 5];
        }
    }
}

extern "C" void kernel_launch(void* const* d_in, const int* in_sizes, int n_in,
                              void* d_out, int out_size){
    // metadata order is INTERLEAVED (b_i, w_i) pairs.
    const float* nf      = (const float*)d_in[0];
    const int*   species = (const int*)  d_in[1];
    const float* b10 = (const float*)d_in[2];
    const float* w10 = (const float*)d_in[3];
    const float* b11 = (const float*)d_in[4];
    const float* w11 = (const float*)d_in[5];
    const float* b20 = (const float*)d_in[6];
    const float* w20 = (const float*)d_in[7];
    const float* b21 = (const float*)d_in[8];
    const float* w21 = (const float*)d_in[9];
    const float* b30 = (const float*)d_in[10];
    const float* w30 = (const float*)d_in[11];
    const float* b31 = (const float*)d_in[12];
    const float* w31 = (const float*)d_in[13];

    const int n_nodes = in_sizes[1];   // species element count (2048, /4 = 512)

    prep_kernel<<<19, 128>>>(b10, b11, b20, b21, b30, b31);
    // 1 block = 4 nodes; warp = (node, colHalf); 4 ch/thread
    mace_kernel<<<n_nodes / 4, 256>>>(nf, species, w10, w11, w20, w21, w30, w31,
                                      (float*)d_out);
}

// round 10
// speedup vs baseline: 1.1708x; 1.0007x over previous
#include <cuda_runtime.h>

typedef unsigned long long u64;

// ---------- packed f32x2 helpers (sm_103a FFMA2 only via PTX) ----------
__device__ __forceinline__ u64 pack2(float lo, float hi){
    u64 r; asm("mov.b64 %0, {%1,%2};" : "=l"(r) : "f"(lo), "f"(hi)); return r;
}
__device__ __forceinline__ void unpack2(u64 v, float &lo, float &hi){
    asm("mov.b64 {%0,%1}, %2;" : "=f"(lo), "=f"(hi) : "l"(v));
}
__device__ __forceinline__ u64 mul2(u64 a, u64 b){
    u64 r; asm("mul.rn.f32x2 %0, %1, %2;" : "=l"(r) : "l"(a), "l"(b)); return r;
}
__device__ __forceinline__ void fma2(u64 &d, u64 a, u64 b){
    asm("fma.rn.f32x2 %0, %1, %2, %0;" : "+l"(d) : "l"(a), "l"(b));
}

// ---------- symmetrized coefficient tables (written by prep each launch) ----
__device__ __align__(16) u64 g_C1[9 * 4];      // deg-1: 9 monos x 4 cols
__device__ __align__(16) u64 g_C2[45 * 8];     // deg-2: 45 monos x 8 cols
__device__ __align__(16) u64 g_C3[165 * 16];   // deg-3: 165 monos x 12 cols,
                                               // padded: col c at (c/3)*4 + c%3

__device__ __forceinline__ float fetch3(const float* __restrict__ b30,
                                        const float* __restrict__ b31,
                                        int i, int j, int k, int c){
    int base = ((i * 9 + j) * 9 + k) * 3;         // b30: (9,9,9,3,1); b31: (9,9,9,3,3)
    if (c < 3) return b30[base + c];
    return b31[base * 3 + (c - 3)];
}

__global__ void prep_kernel(const float* __restrict__ b10, const float* __restrict__ b11,
                            const float* __restrict__ b20, const float* __restrict__ b21,
                            const float* __restrict__ b30, const float* __restrict__ b31){
    int tid = blockIdx.x * blockDim.x + threadIdx.x;

    if (tid < 36){
        int a = tid >> 2, c = tid & 3;
        float v = (c == 0) ? b10[a] : b11[a * 3 + c - 1];
        g_C1[tid] = pack2(v, v);
    }

    int t2 = tid - 64;
    if (t2 >= 0 && t2 < 45 * 8){
        int mono = t2 >> 3, c = t2 & 7;
        int a = 0, rem = mono;
        while (rem >= 9 - a){ rem -= 9 - a; a++; }
        int b = a + rem;                            // a <= b
        float v;
        if (c < 2){                                 // b20: (9,9,2,1)
            v = b20[(a * 9 + b) * 2 + c];
            if (a != b) v += b20[(b * 9 + a) * 2 + c];
        } else {                                    // b21: (9,9,2,3); c-2 = s*3+p
            int sp = c - 2;
            v = b21[(a * 9 + b) * 6 + sp];
            if (a != b) v += b21[(b * 9 + a) * 6 + sp];
        }
        g_C2[t2] = pack2(v, v);
    }

    int t3 = tid - 448;
    if (t3 >= 0 && t3 < 165 * 12){
        int mono = t3 / 12, c = t3 % 12;
        int a = 0, rem = mono;
        while (true){ int cnt = (9 - a) * (10 - a) / 2; if (rem < cnt) break; rem -= cnt; a++; }
        int b = a;
        while (rem >= 9 - b){ rem -= 9 - b; b++; }
        int k = b + rem;                            // a <= b <= k
        float v = fetch3(b30, b31, a, b, k, c);
        if (a == b && b == k){
        } else if (a == b){
            v += fetch3(b30, b31, a, k, b, c) + fetch3(b30, b31, k, a, b, c);
        } else if (b == k){
            v += fetch3(b30, b31, b, a, k, c) + fetch3(b30, b31, b, k, a, c);
        } else {
            v += fetch3(b30, b31, a, k, b, c) + fetch3(b30, b31, b, a, k, c)
               + fetch3(b30, b31, b, k, a, c) + fetch3(b30, b31, k, a, b, c)
               + fetch3(b30, b31, k, b, a, c);
        }
        // padded layout: group of 3 cols per colQ lives at colQ*4 + {0,1,2}
        g_C3[mono * 16 + (c / 3) * 4 + (c % 3)] = pack2(v, v);
    }
}

// ---------- main kernel ------------------------------------------------------
// 1 block = 1 node, 128 threads = 4 warps. Warp id = colQ (WARP-UNIFORM column
// quarter -> all coefficient LDS are lane-identical); lane = channel quad,
// m0 = lane*4 (4 channels/thread as two f32x2 pairs).
//   colQ: C1 col colQ | C2 cols 2colQ..2colQ+1 | C3 cols 3colQ..3colQ+2
// Per-thread accumulators: (1+2+3) cols x 2 ch-pairs = 12 u64 (24 regs).
// Quarters combined through smem partial buffers; colQ-0 warp stores.
__global__ void __launch_bounds__(128) mace_kernel(
    const float* __restrict__ nf, const int* __restrict__ species,
    const float* __restrict__ w10, const float* __restrict__ w11,
    const float* __restrict__ w20, const float* __restrict__ w21,
    const float* __restrict__ w30, const float* __restrict__ w31,
    float* __restrict__ out)
{
    __shared__ __align__(16) u64 sC1[9 * 4];
    __shared__ __align__(16) u64 sC2[45 * 8];
    __shared__ __align__(16) u64 sC3[165 * 16];
    __shared__ float part[3][512];          // partials from colQ 1..3

    const int t = threadIdx.x;
    for (int i = t; i < 36;   i += 128) sC1[i] = g_C1[i];
    for (int i = t; i < 360;  i += 128) sC2[i] = g_C2[i];
    for (int i = t; i < 2640; i += 128) sC3[i] = g_C3[i];
    __syncthreads();

    const int node = blockIdx.x;
    const int colQ = t >> 5;              // warp-uniform column quarter [0,4)
    const int lane = t & 31;
    const int m0   = lane * 4;            // channels m0..m0+3 (pair A, pair B)
    const float* nfp = nf + (size_t)node * 1152;

    // x components fully in registers.
    u64 xA[9], xB[9];
    {
        float4 v = *(const float4*)(nfp + m0);
        xA[0] = pack2(v.x, v.y);
        xB[0] = pack2(v.z, v.w);
    }
    #pragma unroll
    for (int j = 0; j < 3; j++){
        xA[1 + j] = pack2(nfp[128 + m0 * 3 + j],      nfp[128 + m0 * 3 + 3 + j]);
        xB[1 + j] = pack2(nfp[128 + m0 * 3 + 6 + j],  nfp[128 + m0 * 3 + 9 + j]);
    }
    #pragma unroll
    for (int j = 0; j < 5; j++){
        xA[4 + j] = pack2(nfp[512 + m0 * 5 + j],      nfp[512 + m0 * 5 + 5 + j]);
        xB[4 + j] = pack2(nfp[512 + m0 * 5 + 10 + j], nfp[512 + m0 * 5 + 15 + j]);
    }

    // Per-thread accumulators: P1 (C1 col), P2[2] (C2 cols), P3[3] (C3 cols)
    u64 P1A = 0ull, P1B = 0ull;
    u64 P2A[2] = {0ull, 0ull}, P2B[2] = {0ull, 0ull};
    u64 P3A[3] = {0ull, 0ull, 0ull}, P3B[3] = {0ull, 0ull, 0ull};

    const int o2 = colQ * 2;              // warp-uniform offsets
    const int o3 = colQ * 4;

    int i2 = 0, i3 = 0;                       // constant-folded by full unroll
    #pragma unroll
    for (int a = 0; a < 9; a++){
        {
            u64 c = sC1[a * 4 + colQ];
            fma2(P1A, c, xA[a]);  fma2(P1B, c, xB[a]);
        }
        #pragma unroll
        for (int b = a; b < 9; b++){
            u64 pabA = mul2(xA[a], xA[b]);
            u64 pabB = mul2(xB[a], xB[b]);
            {
                ulonglong2 c = *(const ulonglong2*)(sC2 + i2 * 8 + o2);
                fma2(P2A[0], c.x, pabA);  fma2(P2B[0], c.x, pabB);
                fma2(P2A[1], c.y, pabA);  fma2(P2B[1], c.y, pabB);
            }
            i2++;
            #pragma unroll
            for (int k = b; k < 9; k++){
                u64 p3A = mul2(pabA, xA[k]);
                u64 p3B = mul2(pabB, xB[k]);
                const u64* row = sC3 + i3 * 16 + o3;
                ulonglong2 c01 = *(const ulonglong2*)(row);
                u64 c2v = row[2];
                fma2(P3A[0], c01.x, p3A);  fma2(P3B[0], c01.x, p3B);
                fma2(P3A[1], c01.y, p3A);  fma2(P3B[1], c01.y, p3B);
                fma2(P3A[2], c2v,  p3A);   fma2(P3B[2], c2v,  p3B);
                i3++;
            }
        }
    }

    // ---- fold with per-(species, channel) weights (mapping verified in R8) --
    const int sp = species[node];
    const float* W10 = w10 + sp * 128;
    const float* W11 = w11 + sp * 128;
    const float* W20 = w20 + sp * 256;
    const float* W21 = w21 + sp * 256;
    const float* W30 = w30 + sp * 384;
    const float* W31 = w31 + sp * 384;

    u64 O0[2]  = {0ull, 0ull};
    u64 OP0[2] = {0ull, 0ull}, OP1[2] = {0ull, 0ull}, OP2[2] = {0ull, 0ull};

    #pragma unroll
    for (int h = 0; h < 2; h++){
        const int mc = m0 + 2 * h;
        u64 p1 = h ? P1B : P1A;
        u64* p2 = h ? P2B : P2A;
        u64* p3 = h ? P3B : P3A;
        if (colQ == 0){
            fma2(O0[h], *(const u64*)(W10 + mc),       p1);
            fma2(O0[h], *(const u64*)(W20 + mc),       p2[0]);
            fma2(O0[h], *(const u64*)(W20 + 128 + mc), p2[1]);
            fma2(O0[h], *(const u64*)(W30 + mc),       p3[0]);
            fma2(O0[h], *(const u64*)(W30 + 128 + mc), p3[1]);
            fma2(O0[h], *(const u64*)(W30 + 256 + mc), p3[2]);
        } else if (colQ == 1){
            fma2(OP0[h], *(const u64*)(W11 + mc),       p1);
            fma2(OP0[h], *(const u64*)(W21 + mc),       p2[0]);
            fma2(OP1[h], *(const u64*)(W21 + mc),       p2[1]);
            fma2(OP0[h], *(const u64*)(W31 + mc),       p3[0]);
            fma2(OP1[h], *(const u64*)(W31 + mc),       p3[1]);
            fma2(OP2[h], *(const u64*)(W31 + mc),       p3[2]);
        } else if (colQ == 2){
            fma2(OP1[h], *(const u64*)(W11 + mc),       p1);
            fma2(OP2[h], *(const u64*)(W21 + mc),       p2[0]);
            fma2(OP0[h], *(const u64*)(W21 + 128 + mc), p2[1]);
            fma2(OP0[h], *(const u64*)(W31 + 128 + mc), p3[0]);
            fma2(OP1[h], *(const u64*)(W31 + 128 + mc), p3[1]);
            fma2(OP2[h], *(const u64*)(W31 + 128 + mc), p3[2]);
        } else {
            fma2(OP2[h], *(const u64*)(W11 + mc),       p1);
            fma2(OP1[h], *(const u64*)(W21 + 128 + mc), p2[0]);
            fma2(OP2[h], *(const u64*)(W21 + 128 + mc), p2[1]);
            fma2(OP0[h], *(const u64*)(W31 + 256 + mc), p3[0]);
            fma2(OP1[h], *(const u64*)(W31 + 256 + mc), p3[1]);
            fma2(OP2[h], *(const u64*)(W31 + 256 + mc), p3[2]);
        }
    }

    // ---- combine quarters through smem, colQ-0 warp stores -------------------
    float r[16];  // [h][acc: O0,OP0,OP1,OP2][lo/hi]
    #pragma unroll
    for (int h = 0; h < 2; h++){
        unpack2(O0[h],  r[h*8+0], r[h*8+1]);
        unpack2(OP0[h], r[h*8+2], r[h*8+3]);
        unpack2(OP1[h], r[h*8+4], r[h*8+5]);
        unpack2(OP2[h], r[h*8+6], r[h*8+7]);
    }

    if (colQ != 0){
        float* p = part[colQ - 1];
        p[m0 + 0] = r[0];  p[m0 + 1] = r[1];
        p[m0 + 2] = r[8];  p[m0 + 3] = r[9];
        #pragma unroll
        for (int h = 0; h < 2; h++){
            const int mc = m0 + 2 * h;
            p[128 + mc * 3 + 0] = r[h*8+2];  p[128 + mc * 3 + 3] = r[h*8+3];
            p[128 + mc * 3 + 1] = r[h*8+4];  p[128 + mc * 3 + 4] = r[h*8+5];
            p[128 + mc * 3 + 2] = r[h*8+6];  p[128 + mc * 3 + 5] = r[h*8+7];
        }
    }
    __syncthreads();
    if (colQ == 0){
        float* outp = out + (size_t)node * 512;
        float s0 = r[0], s1 = r[1], s2 = r[8], s3 = r[9];
        #pragma unroll
        for (int j = 0; j < 3; j++){
            const float* p = part[j];
            s0 += p[m0 + 0];  s1 += p[m0 + 1];
            s2 += p[m0 + 2];  s3 += p[m0 + 3];
        }
        *(float4*)(outp + m0) = make_float4(s0, s1, s2, s3);

        #pragma unroll
        for (int h = 0; h < 2; h++){
            const int mc = m0 + 2 * h;
            float v0 = r[h*8+2], v3 = r[h*8+3];
            float v1 = r[h*8+4], v4 = r[h*8+5];
            float v2 = r[h*8+6], v5 = r[h*8+7];
            #pragma unroll
            for (int j = 0; j < 3; j++){
                const float* p = part[j];
                v0 += p[128 + mc * 3 + 0];  v3 += p[128 + mc * 3 + 3];
                v1 += p[128 + mc * 3 + 1];  v4 += p[128 + mc * 3 + 4];
                v2 += p[128 + mc * 3 + 2];  v5 += p[128 + mc * 3 + 5];
            }
            outp[128 + mc * 3 + 0] = v0;  outp[128 + mc * 3 + 3] = v3;
            outp[128 + mc * 3 + 1] = v1;  outp[128 + mc * 3 + 4] = v4;
            outp[128 + mc * 3 + 2] = v2;  outp[128 + mc * 3 + 5] = v5;
        }
    }
}

extern "C" void kernel_launch(void* const* d_in, const int* in_sizes, int n_in,
                              void* d_out, int out_size){
    // metadata order is INTERLEAVED (b_i, w_i) pairs.
    const float* nf      = (const float*)d_in[0];
    const int*   species = (const int*)  d_in[1];
    const float* b10 = (const float*)d_in[2];
    const float* w10 = (const float*)d_in[3];
    const float* b11 = (const float*)d_in[4];
    const float* w11 = (const float*)d_in[5];
    const float* b20 = (const float*)d_in[6];
    const float* w20 = (const float*)d_in[7];
    const float* b21 = (const float*)d_in[8];
    const float* w21 = (const float*)d_in[9];
    const float* b30 = (const float*)d_in[10];
    const float* w30 = (const float*)d_in[11];
    const float* b31 = (const float*)d_in[12];
    const float* w31 = (const float*)d_in[13];

    const int n_nodes = in_sizes[1];   // species element count (2048)

    prep_kernel<<<19, 128>>>(b10, b11, b20, b21, b30, b31);
    // 1 block = 1 node, 4 warps = 4 warp-uniform column quarters, 4 ch/thread
    mace_kernel<<<n_nodes, 128>>>(nf, species, w10, w11, w20, w21, w30, w31,
                                  (float*)d_out);
}